// round 9
// baseline (speedup 1.0000x reference)
#include <cuda_runtime.h>

#define SEQ    524288
#define IN_D   5
#define HID    10
#define CHUNK  16
#define WARM   12
#define NBLK   512                  // 512 blocks * 32 lanes * 2 chains = 32768 chunks
#define L2E2   2.8853900817779268f  // 2 * log2(e)

typedef unsigned long long u64;

// smem xp layout: [s(16)][jp(5)][col(66)] float2. Byte strides:
#define S_STR  2640                 // 5*66*8
#define JP_STR 528                  // 66*8

// ---------------------------------------------------------------------------
__device__ __forceinline__ u64 ffma2(u64 a, u64 b, u64 c)
{
    u64 d;
    asm("fma.rn.f32x2 %0, %1, %2, %3;" : "=l"(d) : "l"(a), "l"(b), "l"(c));
    return d;
}
__device__ __forceinline__ u64 pack2(float lo, float hi)
{
    u64 d;
    asm("mov.b64 %0, {%1, %2};" : "=l"(d) : "f"(lo), "f"(hi));
    return d;
}
__device__ __forceinline__ void unpack2(u64 v, float& lo, float& hi)
{
    asm("mov.b64 {%0, %1}, %2;" : "=f"(lo), "=f"(hi) : "l"(v));
}
__device__ __forceinline__ float ex2f(float x)
{
    float e; asm("ex2.approx.f32 %0, %1;" : "=f"(e) : "f"(x)); return e;
}
__device__ __forceinline__ float rcpf(float x)
{
    float r; asm("rcp.approx.f32 %0, %1;" : "=f"(r) : "f"(x)); return r;
}

__device__ __forceinline__ u64 lds64(const char* p)
{
    return *reinterpret_cast<const u64*>(p);
}

// ---------------------------------------------------------------------------
// One dual-chain RNN step. Consumes xqA/xqB, refills them from pA/pB + ROFF
// (byte offset of the NEXT step's slot), advances hdA/hdB. Chains A and B are
// fully independent -> ILP covers the dependence chains.
// ---------------------------------------------------------------------------
#define STEP2(ROFF, DO_OUT, OI)                                                \
{                                                                              \
    u64 aA[5], aB[5];                                                          \
    _Pragma("unroll")                                                          \
    for (int jp = 0; jp < 5; jp++) {                                           \
        aA[jp] = ffma2(wp[jp][0], hdA[0], xqA[jp]);                            \
        aB[jp] = ffma2(wp[jp][0], hdB[0], xqB[jp]);                            \
    }                                                                          \
    _Pragma("unroll")                                                          \
    for (int jp = 0; jp < 5; jp++) {                                           \
        xqA[jp] = lds64(pA + (ROFF) + jp * JP_STR);                            \
        xqB[jp] = lds64(pB + (ROFF) + jp * JP_STR);                            \
    }                                                                          \
    _Pragma("unroll")                                                          \
    for (int k = 1; k < HID; k++) {                                            \
        _Pragma("unroll")                                                      \
        for (int jp = 0; jp < 5; jp++) {                                       \
            aA[jp] = ffma2(wp[jp][k], hdA[k], aA[jp]);                         \
            aB[jp] = ffma2(wp[jp][k], hdB[k], aB[jp]);                         \
        }                                                                      \
    }                                                                          \
    float hhA[HID], hhB[HID];                                                  \
    _Pragma("unroll")                                                          \
    for (int jp = 0; jp < 5; jp++) {                                           \
        float zl, zh;                                                          \
        unpack2(aA[jp], zl, zh);                                               \
        const float A1 = ex2f(zl) + 1.0f;                                      \
        const float B1 = ex2f(zh) + 1.0f;                                      \
        const float u1 = -2.0f * rcpf(A1 * B1);                                \
        hhA[2 * jp]     = fmaf(u1, B1, 1.0f);                                  \
        hhA[2 * jp + 1] = fmaf(u1, A1, 1.0f);                                  \
        unpack2(aB[jp], zl, zh);                                               \
        const float A2 = ex2f(zl) + 1.0f;                                      \
        const float B2 = ex2f(zh) + 1.0f;                                      \
        const float u2 = -2.0f * rcpf(A2 * B2);                                \
        hhB[2 * jp]     = fmaf(u2, B2, 1.0f);                                  \
        hhB[2 * jp + 1] = fmaf(u2, A2, 1.0f);                                  \
    }                                                                          \
    _Pragma("unroll")                                                          \
    for (int j = 0; j < HID; j++) {                                            \
        hdA[j] = pack2(hhA[j], hhA[j]);                                        \
        hdB[j] = pack2(hhB[j], hhB[j]);                                        \
    }                                                                          \
    if (DO_OUT) {                                                              \
        float oA = bf, oB = bf;                                                \
        _Pragma("unroll")                                                      \
        for (int j = 0; j < HID; j++) {                                        \
            oA = fmaf(wf[j], hhA[j], oA);                                      \
            oB = fmaf(wf[j], hhB[j], oB);                                      \
        }                                                                      \
        srow[OI] = oA;                                                         \
        srow[(OI) + 544] = oB;                                                 \
    }                                                                          \
}

// ---------------------------------------------------------------------------
// Fused kernel: one warp = 64 chunks (2 per lane). Window = 65 columns of 16
// timesteps. Lane L: chain A = chunk c0+L (warmup col L slots 4..15, output
// col L+1), chain B = chunk c0+32+L (cols +32). t<0 -> xp = 0 exactly, so
// chunk 0's warmup keeps h == 0 (exact).
// ---------------------------------------------------------------------------
__global__ void __launch_bounds__(32, 1) rnn_fused_kernel(
    const float* __restrict__ src,    // (SEQ, 1, IN_D)
    const float* __restrict__ W_ih,   // (HID, IN_D)
    const float* __restrict__ W_hh,   // (HID, HID)
    const float* __restrict__ b_ih,   // (HID,)
    const float* __restrict__ b_hh,   // (HID,)
    const float* __restrict__ W_fc,   // (1, HID)
    const float* __restrict__ b_fc,   // (1,)
    float* __restrict__ out)          // (SEQ,)
{
    __shared__ float2 sxp[16 * 5 * 66];           // 42240 B
    __shared__ alignas(16) float sraw[1300];      // 5200 B; reused for outputs

    const int lane = threadIdx.x;
    const long b   = blockIdx.x;
    const long t0  = b * 1024 - 16;               // window origin timestep

    // ---- per-lane input weights (pre-scaled by 2*log2e) ----
    float wih[HID][IN_D], bias[HID];
#pragma unroll
    for (int j = 0; j < HID; j++) {
        bias[j] = (b_ih[j] + b_hh[j]) * L2E2;
#pragma unroll
        for (int k = 0; k < IN_D; k++) wih[j][k] = W_ih[j * IN_D + k] * L2E2;
    }

    // ---- stage + compute xp, 4 passes of 260 timesteps ----
#pragma unroll 1
    for (int p = 0; p < 4; p++) {
        const int u0 = p * 260;
        const long fb = t0 * IN_D + (long)p * 1300;   // 16B-aligned
        // raw load: 325 float4 (zero-filled outside [0, SEQ*IN_D))
#pragma unroll 1
        for (int i = lane; i < 325; i += 32) {
            float4 v = make_float4(0.f, 0.f, 0.f, 0.f);
            const long f = fb + (long)i * 4;
            if (f >= 0 && f < (long)SEQ * IN_D)
                v = *reinterpret_cast<const float4*>(src + f);
            reinterpret_cast<float4*>(sraw)[i] = v;
        }
        __syncwarp();
        // xp for 260 timesteps (zero when t < 0)
#pragma unroll 1
        for (int kk = 0; kk < 9; kk++) {
            const int ul = lane + 32 * kk;
            if (ul < 260) {
                const int u = u0 + ul;
                const float* sp = sraw + ul * IN_D;
                const float s0 = sp[0], s1 = sp[1], s2 = sp[2], s3 = sp[3], s4 = sp[4];
                const bool neg = (t0 + u) < 0;
                float2* dst = &sxp[((u & 15) * 5) * 66 + (u >> 4)];
#pragma unroll
                for (int jp = 0; jp < 5; jp++) {
                    float vl = bias[2 * jp], vh = bias[2 * jp + 1];
                    vl = fmaf(s0, wih[2 * jp][0], vl);  vh = fmaf(s0, wih[2 * jp + 1][0], vh);
                    vl = fmaf(s1, wih[2 * jp][1], vl);  vh = fmaf(s1, wih[2 * jp + 1][1], vh);
                    vl = fmaf(s2, wih[2 * jp][2], vl);  vh = fmaf(s2, wih[2 * jp + 1][2], vh);
                    vl = fmaf(s3, wih[2 * jp][3], vl);  vh = fmaf(s3, wih[2 * jp + 1][3], vh);
                    vl = fmaf(s4, wih[2 * jp][4], vl);  vh = fmaf(s4, wih[2 * jp + 1][4], vh);
                    if (neg) { vl = 0.0f; vh = 0.0f; }
                    dst[jp * 66] = make_float2(vl, vh);
                }
            }
        }
        __syncwarp();
    }

    // ---- recurrent weights (packed, pre-scaled) + readout weights ----
    u64 wp[5][HID];
#pragma unroll
    for (int jp = 0; jp < 5; jp++)
#pragma unroll
        for (int k = 0; k < HID; k++)
            wp[jp][k] = pack2(W_hh[(2 * jp) * HID + k] * L2E2,
                              W_hh[(2 * jp + 1) * HID + k] * L2E2);
    float wf[HID];
#pragma unroll
    for (int j = 0; j < HID; j++) wf[j] = W_fc[j];
    const float bf = b_fc[0];

    u64 hdA[HID], hdB[HID];
#pragma unroll
    for (int j = 0; j < HID; j++) { hdA[j] = pack2(0.f, 0.f); hdB[j] = pack2(0.f, 0.f); }

    const char* pA = reinterpret_cast<const char*>(sxp) + lane * 8;       // chain A cols
    const char* pB = pA + 32 * 8;                                          // chain B cols
    float* srow = sraw + lane * 17;              // outputs: [chunk-local][slot], stride 17

    // preload step 0 data (warmup col, slot 4)
    u64 xqA[5], xqB[5];
#pragma unroll
    for (int jp = 0; jp < 5; jp++) {
        xqA[jp] = lds64(pA + 4 * S_STR + jp * JP_STR);
        xqB[jp] = lds64(pB + 4 * S_STR + jp * JP_STR);
    }

    // ---- warmup: si = 0..11 (consume warmup col slots 4..15) ----
    {
        const char* pf = pA + 5 * S_STR;   // refill offsets tracked relative to pA
        int off = 5 * S_STR;
#pragma unroll 1
        for (int it = 0; it < 5; it++) {   // si = 0..9, refills slots 5..14
            STEP2(off, false, 0)
            STEP2(off + S_STR, false, 0)
            off += 2 * S_STR;
        }
        STEP2(off, false, 0)               // si = 10, refill slot 15
        STEP2(8, false, 0)                 // si = 11, refill output col slot 0 (+8B = col+1)
        (void)pf;
    }

    // ---- output: si = 12..27 (consume output col slots 0..15) ----
    {
        int off = 8 + S_STR;               // refill output col slot 1
#pragma unroll 1
        for (int it = 0; it < 7; it++) {   // si = 12..25, refills slots 1..14
            STEP2(off, true, 0)
            STEP2(off + S_STR, true, 1)
            off += 2 * S_STR;
            srow += 2;
        }
        STEP2(off, true, 0)                // si = 26, refill slot 15
        STEP2(off, true, 1)                // si = 27, dummy refill (discarded)
    }

    __syncwarp();

    // ---- coalesced flush: this block owns out[b*1024 .. +1024) ----
    float* ob = out + (size_t)b * 1024;
#pragma unroll 1
    for (int i = 0; i < 32; i++) {
        const int idx = i * 32 + lane;
        ob[idx] = sraw[(idx >> 4) * 17 + (idx & 15)];
    }
}

// ---------------------------------------------------------------------------
extern "C" void kernel_launch(void* const* d_in, const int* in_sizes, int n_in,
                              void* d_out, int out_size)
{
    const float* src  = (const float*)d_in[0];
    const float* W_ih = (const float*)d_in[1];
    const float* W_hh = (const float*)d_in[2];
    const float* b_ih = (const float*)d_in[3];
    const float* b_hh = (const float*)d_in[4];
    const float* W_fc = (const float*)d_in[5];
    const float* b_fc = (const float*)d_in[6];
    float* out = (float*)d_out;

    rnn_fused_kernel<<<NBLK, 32>>>(src, W_ih, W_hh, b_ih, b_hh, W_fc, b_fc, out);
}

// round 10
// speedup vs baseline: 1.4332x; 1.4332x over previous
#include <cuda_runtime.h>

#define SEQ    524288
#define IN_D   5
#define HID    10
#define CHUNK  16
#define WARM   10
#define NST    26
#define NBLK   1024                 // 1024 blocks * 32 lanes = 32768 chunks
#define L2E2   2.8853900817779268f  // 2 * log2(e)

// smem xp layout: [s(16)][jp(5)][col(33)] float2; byte strides:
#define S_STR  1320                 // 5*33*8
#define JP_STR 264                  // 33*8

__device__ __forceinline__ float ex2f(float x)
{
    float e; asm("ex2.approx.f32 %0, %1;" : "=f"(e) : "f"(x)); return e;
}
__device__ __forceinline__ float rcpf(float x)
{
    float r; asm("rcp.approx.f32 %0, %1;" : "=f"(r) : "f"(x)); return r;
}

// ---------------------------------------------------------------------------
// One scalar RNN step. Consume xq[J]; optionally refill xq[J] (float2 LDS.64
// at compile-time offset ROFF from pbase); dual-accumulator matvec; paired-
// reciprocal tanh (args pre-scaled by 2*log2e).
// ---------------------------------------------------------------------------
#define STEP(J, ROFF, DO_REFILL, DO_OUT, OI)                                   \
{                                                                              \
    float xv[HID];                                                             \
    _Pragma("unroll")                                                          \
    for (int jp = 0; jp < 5; jp++) {                                           \
        xv[2 * jp]     = xq[J][jp].x;                                          \
        xv[2 * jp + 1] = xq[J][jp].y;                                          \
    }                                                                          \
    float a0[HID], a1[HID];                                                    \
    _Pragma("unroll")                                                          \
    for (int j = 0; j < HID; j++) {                                            \
        a0[j] = fmaf(w[0][j], h[0], xv[j]);                                    \
        a1[j] = w[5][j] * h[5];                                                \
    }                                                                          \
    if (DO_REFILL) {                                                           \
        _Pragma("unroll")                                                      \
        for (int jp = 0; jp < 5; jp++)                                         \
            xq[J][jp] = *reinterpret_cast<const float2*>(                      \
                            pbase + (ROFF) + jp * JP_STR);                     \
    }                                                                          \
    _Pragma("unroll")                                                          \
    for (int k = 1; k < 5; k++) {                                              \
        _Pragma("unroll")                                                      \
        for (int j = 0; j < HID; j++) {                                        \
            a0[j] = fmaf(w[k][j],     h[k],     a0[j]);                        \
            a1[j] = fmaf(w[k + 5][j], h[k + 5], a1[j]);                        \
        }                                                                      \
    }                                                                          \
    _Pragma("unroll")                                                          \
    for (int jp = 0; jp < 5; jp++) {                                           \
        const float zl = a0[2 * jp]     + a1[2 * jp];                          \
        const float zh = a0[2 * jp + 1] + a1[2 * jp + 1];                      \
        const float A = ex2f(zl) + 1.0f;                                       \
        const float B = ex2f(zh) + 1.0f;                                       \
        const float u = -2.0f * rcpf(A * B);                                   \
        h[2 * jp]     = fmaf(u, B, 1.0f);                                      \
        h[2 * jp + 1] = fmaf(u, A, 1.0f);                                      \
    }                                                                          \
    if (DO_OUT) {                                                              \
        float o = bf;                                                          \
        _Pragma("unroll")                                                      \
        for (int j = 0; j < HID; j++) o = fmaf(wf[j], h[j], o);                \
        srow[OI] = o;                                                          \
    }                                                                          \
}

// ---------------------------------------------------------------------------
// Fused kernel: one warp = 32 chunks (one per lane). Stage 33-column window
// (528 timesteps) -> xp in smem -> 10 warmup + 16 output steps -> flush.
// Lane L: warmup = col L slots 6..15 (tail of previous chunk), output =
// col L+1 slots 0..15. t<0 -> xp = 0 exactly (chunk 0 warmup keeps h == 0).
// ---------------------------------------------------------------------------
__global__ void __launch_bounds__(32, 1) rnn_fused_kernel(
    const float* __restrict__ src,    // (SEQ, 1, IN_D)
    const float* __restrict__ W_ih,   // (HID, IN_D)
    const float* __restrict__ W_hh,   // (HID, HID)
    const float* __restrict__ b_ih,   // (HID,)
    const float* __restrict__ b_hh,   // (HID,)
    const float* __restrict__ W_fc,   // (1, HID)
    const float* __restrict__ b_fc,   // (1,)
    float* __restrict__ out)          // (SEQ,)
{
    __shared__ float2 sxp[16 * 5 * 33 + 4];       // 21152 B
    __shared__ alignas(16) float sraw[1336];      // staging; reused for outputs

    const int lane = threadIdx.x;
    const int c0   = blockIdx.x * 32;

    // ---- input weights (pre-scaled by 2*log2e) ----
    float wih[HID][IN_D], bias[HID];
#pragma unroll
    for (int j = 0; j < HID; j++) {
        bias[j] = (b_ih[j] + b_hh[j]) * L2E2;
#pragma unroll
        for (int k = 0; k < IN_D; k++) wih[j][k] = W_ih[j * IN_D + k] * L2E2;
    }

    // ---- stage + compute xp, two halves of 264 timesteps ----
    const long t0  = ((long)c0 - 1) * 16;         // window origin timestep
    const long f00 = t0 * IN_D;                   // float index (16B-aligned)
#pragma unroll 1
    for (int half = 0; half < 2; half++) {
        const long fb = f00 + half * 1320;
#pragma unroll 1
        for (int i = lane; i < 330; i += 32) {
            float4 v = make_float4(0.f, 0.f, 0.f, 0.f);
            const long f = fb + (long)i * 4;
            if (f >= 0) v = *reinterpret_cast<const float4*>(src + f);
            reinterpret_cast<float4*>(sraw)[i] = v;
        }
        __syncwarp();
#pragma unroll 1
        for (int kk = 0; kk < 9; kk++) {
            const int ul = lane + 32 * kk;
            if (ul < 264) {
                const int u = half * 264 + ul;
                const float* sp = sraw + ul * IN_D;
                const float s0 = sp[0], s1 = sp[1], s2 = sp[2], s3 = sp[3], s4 = sp[4];
                const bool neg = (t0 + u) < 0;
                float2* dst = &sxp[((u & 15) * 5) * 33 + (u >> 4)];
#pragma unroll
                for (int jp = 0; jp < 5; jp++) {
                    float vl = bias[2 * jp], vh = bias[2 * jp + 1];
                    vl = fmaf(s0, wih[2 * jp][0], vl);  vh = fmaf(s0, wih[2 * jp + 1][0], vh);
                    vl = fmaf(s1, wih[2 * jp][1], vl);  vh = fmaf(s1, wih[2 * jp + 1][1], vh);
                    vl = fmaf(s2, wih[2 * jp][2], vl);  vh = fmaf(s2, wih[2 * jp + 1][2], vh);
                    vl = fmaf(s3, wih[2 * jp][3], vl);  vh = fmaf(s3, wih[2 * jp + 1][3], vh);
                    vl = fmaf(s4, wih[2 * jp][4], vl);  vh = fmaf(s4, wih[2 * jp + 1][4], vh);
                    if (neg) { vl = 0.0f; vh = 0.0f; }
                    dst[jp * 33] = make_float2(vl, vh);
                }
            }
        }
        __syncwarp();
    }

    // ---- recurrent weights (k-major, pre-scaled) + readout weights ----
    float w[HID][HID];                 // w[k][j] = W_hh[j][k] * 2log2e
#pragma unroll
    for (int k = 0; k < HID; k++)
#pragma unroll
        for (int j = 0; j < HID; j++)
            w[k][j] = W_hh[j * HID + k] * L2E2;
    float wf[HID];
#pragma unroll
    for (int j = 0; j < HID; j++) wf[j] = W_fc[j];
    const float bf = b_fc[0];

    float h[HID];
#pragma unroll
    for (int j = 0; j < HID; j++) h[j] = 0.0f;

    // pbase at lane's warmup column; output column = +8 bytes (col+1)
    const char* pbase = reinterpret_cast<const char*>(sxp) + lane * 8;
    float* srow = sraw + lane * 17;   // outputs: stride-17, conflict-free

    // preload warmup col slots 6,7
    float2 xq[2][5];
#pragma unroll
    for (int jp = 0; jp < 5; jp++) {
        xq[0][jp] = *reinterpret_cast<const float2*>(pbase + 6 * S_STR + jp * JP_STR);
        xq[1][jp] = *reinterpret_cast<const float2*>(pbase + 7 * S_STR + jp * JP_STR);
    }

    // ---- warmup: si = 0..9 (consume warmup col slots 6..15) ----
#pragma unroll 1
    for (int it = 0; it < 4; it++) {             // si = 0..7, refill slots 8..15
        const int off = (8 + 2 * it) * S_STR;
        STEP(0, off, true, false, 0)
        STEP(1, off + S_STR, true, false, 0)
    }
    STEP(0, 8 + 0 * S_STR, true, false, 0)       // si = 8, refill output slot 0
    STEP(1, 8 + 1 * S_STR, true, false, 0)       // si = 9, refill output slot 1

    // ---- output: si = 10..25 (consume output col slots 0..15) ----
#pragma unroll 1
    for (int it = 0; it < 7; it++) {             // si = 10..23, refill slots 2..15
        const int off = 8 + (2 + 2 * it) * S_STR;
        STEP(0, off, true, true, 0)
        STEP(1, off + S_STR, true, true, 1)
        srow += 2;
    }
    STEP(0, 8, false, true, 0)                   // si = 24 (no refill)
    STEP(1, 8, false, true, 1)                   // si = 25 (no refill)

    __syncwarp();

    // ---- coalesced flush: this block owns out[blockIdx*512 .. +512) ----
    float* ob = out + (size_t)blockIdx.x * 512;
#pragma unroll
    for (int i = 0; i < 16; i++) {
        const int idx = i * 32 + lane;
        ob[idx] = sraw[(idx >> 4) * 17 + (idx & 15)];
    }
}

// ---------------------------------------------------------------------------
extern "C" void kernel_launch(void* const* d_in, const int* in_sizes, int n_in,
                              void* d_out, int out_size)
{
    const float* src  = (const float*)d_in[0];
    const float* W_ih = (const float*)d_in[1];
    const float* W_hh = (const float*)d_in[2];
    const float* b_ih = (const float*)d_in[3];
    const float* b_hh = (const float*)d_in[4];
    const float* W_fc = (const float*)d_in[5];
    const float* b_fc = (const float*)d_in[6];
    float* out = (float*)d_out;

    rnn_fused_kernel<<<NBLK, 32>>>(src, W_ih, W_hh, b_ih, b_hh, W_fc, b_fc, out);
}

// round 11
// speedup vs baseline: 1.6072x; 1.1214x over previous
#include <cuda_runtime.h>

#define SEQ    524288
#define IN_D   5
#define HID    10
#define CHUNK  16
#define WARM   10
#define NST    26
#define NBLK   1024                 // 1024 blocks * 32 lanes = 32768 chunks
#define L2E2   2.8853900817779268f  // 2 * log2(e)

// smem xp layout: [s(16)][jp(5)][col(33)] float2; byte strides:
#define S_STR  1320                 // 5*33*8
#define JP_STR 264                  // 33*8

#define WIN_T     528               // 33 cols * 16 timesteps
#define WIN_BYTES (WIN_T * IN_D * 4)   // 10560

__device__ __forceinline__ float ex2f(float x)
{
    float e; asm("ex2.approx.f32 %0, %1;" : "=f"(e) : "f"(x)); return e;
}
__device__ __forceinline__ float rcpf(float x)
{
    float r; asm("rcp.approx.f32 %0, %1;" : "=f"(r) : "f"(x)); return r;
}
__device__ __forceinline__ unsigned smem_u32(const void* p)
{
    unsigned a;
    asm("{ .reg .u64 t; cvta.to.shared.u64 t, %1; cvt.u32.u64 %0, t; }"
        : "=r"(a) : "l"(p));
    return a;
}

// ---------------------------------------------------------------------------
// One scalar RNN step (identical math to round 10).
// ---------------------------------------------------------------------------
#define STEP(J, ROFF, DO_REFILL, DO_OUT, OI)                                   \
{                                                                              \
    float xv[HID];                                                             \
    _Pragma("unroll")                                                          \
    for (int jp = 0; jp < 5; jp++) {                                           \
        xv[2 * jp]     = xq[J][jp].x;                                          \
        xv[2 * jp + 1] = xq[J][jp].y;                                          \
    }                                                                          \
    float a0[HID], a1[HID];                                                    \
    _Pragma("unroll")                                                          \
    for (int j = 0; j < HID; j++) {                                            \
        a0[j] = fmaf(w[0][j], h[0], xv[j]);                                    \
        a1[j] = w[5][j] * h[5];                                                \
    }                                                                          \
    if (DO_REFILL) {                                                           \
        _Pragma("unroll")                                                      \
        for (int jp = 0; jp < 5; jp++)                                         \
            xq[J][jp] = *reinterpret_cast<const float2*>(                      \
                            pbase + (ROFF) + jp * JP_STR);                     \
    }                                                                          \
    _Pragma("unroll")                                                          \
    for (int k = 1; k < 5; k++) {                                              \
        _Pragma("unroll")                                                      \
        for (int j = 0; j < HID; j++) {                                        \
            a0[j] = fmaf(w[k][j],     h[k],     a0[j]);                        \
            a1[j] = fmaf(w[k + 5][j], h[k + 5], a1[j]);                        \
        }                                                                      \
    }                                                                          \
    _Pragma("unroll")                                                          \
    for (int jp = 0; jp < 5; jp++) {                                           \
        const float zl = a0[2 * jp]     + a1[2 * jp];                          \
        const float zh = a0[2 * jp + 1] + a1[2 * jp + 1];                      \
        const float A = ex2f(zl) + 1.0f;                                       \
        const float B = ex2f(zh) + 1.0f;                                       \
        const float u = -2.0f * rcpf(A * B);                                   \
        h[2 * jp]     = fmaf(u, B, 1.0f);                                      \
        h[2 * jp + 1] = fmaf(u, A, 1.0f);                                      \
    }                                                                          \
    if (DO_OUT) {                                                              \
        float o = bf;                                                          \
        _Pragma("unroll")                                                      \
        for (int j = 0; j < HID; j++) o = fmaf(wf[j], h[j], o);                \
        srow[OI] = o;                                                          \
    }                                                                          \
}

// ---------------------------------------------------------------------------
// Fused kernel: one warp = 32 chunks (one per lane).
// Staging is ONE cp.async.bulk (10.5 KB GMEM->SMEM, no L1tex wavefronts),
// overlapped with weight-register setup; then xp compute; then 26-step scan.
// ---------------------------------------------------------------------------
__global__ void __launch_bounds__(32, 1) rnn_fused_kernel(
    const float* __restrict__ src,    // (SEQ, 1, IN_D)
    const float* __restrict__ W_ih,   // (HID, IN_D)
    const float* __restrict__ W_hh,   // (HID, HID)
    const float* __restrict__ b_ih,   // (HID,)
    const float* __restrict__ b_hh,   // (HID,)
    const float* __restrict__ W_fc,   // (1, HID)
    const float* __restrict__ b_fc,   // (1,)
    float* __restrict__ out)          // (SEQ,)
{
    __shared__ float2 sxp[16 * 5 * 33 + 4];            // 21152 B
    __shared__ alignas(16) float sraw[WIN_T * IN_D];   // 10560 B; reused for outputs
    __shared__ alignas(8) unsigned long long mbar;

    const int lane = threadIdx.x;
    const int c0   = blockIdx.x * 32;
    const long t0  = ((long)c0 - 1) * 16;              // window origin (−16 for block 0)

    // ---- issue the bulk DMA first (completion signaled on mbar) ----
    if (lane == 0) {
        asm volatile("mbarrier.init.shared.b64 [%0], %1;"
                     :: "r"(smem_u32(&mbar)), "r"(1) : "memory");
    }
    __syncwarp();
    if (lane == 0) {
        // block 0: clamp source to t=0, shift destination by 16 timesteps.
        const bool  b0   = (blockIdx.x == 0);
        const int   skip = b0 ? 16 * IN_D * 4 : 0;     // 320 B
        const int   size = WIN_BYTES - skip;
        const char* gsrc = reinterpret_cast<const char*>(src) + t0 * IN_D * 4 + skip;
        const unsigned dst = smem_u32(sraw) + skip;
        asm volatile("mbarrier.arrive.expect_tx.shared.b64 _, [%0], %1;"
                     :: "r"(smem_u32(&mbar)), "r"(size) : "memory");
        asm volatile("cp.async.bulk.shared::cta.global.mbarrier::complete_tx::bytes"
                     " [%0], [%1], %2, [%3];"
                     :: "r"(dst), "l"(gsrc), "r"(size), "r"(smem_u32(&mbar))
                     : "memory");
    }

    // ---- overlap: load all weights into registers while the DMA flies ----
    float wih[HID][IN_D], bias[HID];
#pragma unroll
    for (int j = 0; j < HID; j++) {
        bias[j] = (b_ih[j] + b_hh[j]) * L2E2;
#pragma unroll
        for (int k = 0; k < IN_D; k++) wih[j][k] = W_ih[j * IN_D + k] * L2E2;
    }
    float w[HID][HID];                 // w[k][j] = W_hh[j][k] * 2log2e
#pragma unroll
    for (int k = 0; k < HID; k++)
#pragma unroll
        for (int j = 0; j < HID; j++)
            w[k][j] = W_hh[j * HID + k] * L2E2;
    float wf[HID];
#pragma unroll
    for (int j = 0; j < HID; j++) wf[j] = W_fc[j];
    const float bf = b_fc[0];

    // ---- wait for DMA ----
    {
        const unsigned mb = smem_u32(&mbar);
        unsigned done;
        asm volatile(
            "{\n\t"
            ".reg .pred p;\n\t"
            "WAIT_%=:\n\t"
            "mbarrier.try_wait.parity.acquire.cta.shared::cta.b64 p, [%1], 0;\n\t"
            "@p bra.uni DONE_%=;\n\t"
            "bra.uni WAIT_%=;\n\t"
            "DONE_%=:\n\t"
            "mov.u32 %0, 1;\n\t"
            "}"
            : "=r"(done) : "r"(mb) : "memory");
    }
    __syncwarp();

    // ---- compute xp into sxp (t < 0 -> exact zeros; sraw garbage discarded) ----
#pragma unroll 1
    for (int kk = 0; kk < 17; kk++) {
        const int u = lane + 32 * kk;
        if (u < WIN_T) {
            const float* sp = sraw + u * IN_D;
            const float s0 = sp[0], s1 = sp[1], s2 = sp[2], s3 = sp[3], s4 = sp[4];
            const bool neg = (t0 + u) < 0;
            float2* dst = &sxp[((u & 15) * 5) * 33 + (u >> 4)];
#pragma unroll
            for (int jp = 0; jp < 5; jp++) {
                float vl = bias[2 * jp], vh = bias[2 * jp + 1];
                vl = fmaf(s0, wih[2 * jp][0], vl);  vh = fmaf(s0, wih[2 * jp + 1][0], vh);
                vl = fmaf(s1, wih[2 * jp][1], vl);  vh = fmaf(s1, wih[2 * jp + 1][1], vh);
                vl = fmaf(s2, wih[2 * jp][2], vl);  vh = fmaf(s2, wih[2 * jp + 1][2], vh);
                vl = fmaf(s3, wih[2 * jp][3], vl);  vh = fmaf(s3, wih[2 * jp + 1][3], vh);
                vl = fmaf(s4, wih[2 * jp][4], vl);  vh = fmaf(s4, wih[2 * jp + 1][4], vh);
                if (neg) { vl = 0.0f; vh = 0.0f; }
                dst[jp * 33] = make_float2(vl, vh);
            }
        }
    }
    __syncwarp();

    // ---- scan state ----
    float h[HID];
#pragma unroll
    for (int j = 0; j < HID; j++) h[j] = 0.0f;

    const char* pbase = reinterpret_cast<const char*>(sxp) + lane * 8;
    float* srow = sraw + lane * 17;   // outputs: stride-17, conflict-free

    // preload warmup col slots 6,7
    float2 xq[2][5];
#pragma unroll
    for (int jp = 0; jp < 5; jp++) {
        xq[0][jp] = *reinterpret_cast<const float2*>(pbase + 6 * S_STR + jp * JP_STR);
        xq[1][jp] = *reinterpret_cast<const float2*>(pbase + 7 * S_STR + jp * JP_STR);
    }

    // ---- warmup: si = 0..9 (consume warmup col slots 6..15) ----
#pragma unroll 1
    for (int it = 0; it < 4; it++) {             // si = 0..7, refill slots 8..15
        const int off = (8 + 2 * it) * S_STR;
        STEP(0, off, true, false, 0)
        STEP(1, off + S_STR, true, false, 0)
    }
    STEP(0, 8 + 0 * S_STR, true, false, 0)       // si = 8, refill output slot 0
    STEP(1, 8 + 1 * S_STR, true, false, 0)       // si = 9, refill output slot 1

    // ---- output: si = 10..25 (consume output col slots 0..15) ----
#pragma unroll 1
    for (int it = 0; it < 7; it++) {             // si = 10..23, refill slots 2..15
        const int off = 8 + (2 + 2 * it) * S_STR;
        STEP(0, off, true, true, 0)
        STEP(1, off + S_STR, true, true, 1)
        srow += 2;
    }
    STEP(0, 8, false, true, 0)                   // si = 24 (no refill)
    STEP(1, 8, false, true, 1)                   // si = 25 (no refill)

    __syncwarp();

    // ---- coalesced flush: this block owns out[blockIdx*512 .. +512) ----
    float* ob = out + (size_t)blockIdx.x * 512;
#pragma unroll
    for (int i = 0; i < 16; i++) {
        const int idx = i * 32 + lane;
        ob[idx] = sraw[(idx >> 4) * 17 + (idx & 15)];
    }
}

// ---------------------------------------------------------------------------
extern "C" void kernel_launch(void* const* d_in, const int* in_sizes, int n_in,
                              void* d_out, int out_size)
{
    const float* src  = (const float*)d_in[0];
    const float* W_ih = (const float*)d_in[1];
    const float* W_hh = (const float*)d_in[2];
    const float* b_ih = (const float*)d_in[3];
    const float* b_hh = (const float*)d_in[4];
    const float* W_fc = (const float*)d_in[5];
    const float* b_fc = (const float*)d_in[6];
    float* out = (float*)d_out;

    rnn_fused_kernel<<<NBLK, 32>>>(src, W_ih, W_hh, b_ih, b_hh, W_fc, b_fc, out);
}

// round 12
// speedup vs baseline: 1.8822x; 1.1711x over previous
#include <cuda_runtime.h>

#define SEQ    524288
#define IN_D   5
#define HID    10
#define CHUNK  16
#define WARM   10
#define NST    26
#define NBLK   1024                 // 1024 blocks * 32 lanes = 32768 chunks

// smem xp layout: [s(16)][jp(5)][col(33)] float2; byte strides:
#define S_STR  1320                 // 5*33*8
#define JP_STR 264                  // 33*8

#define WIN_T     528               // 33 cols * 16 timesteps
#define WIN_BYTES (WIN_T * IN_D * 4)   // 10560

__device__ __forceinline__ float tanhf_hw(float x)
{
    float t; asm("tanh.approx.f32 %0, %1;" : "=f"(t) : "f"(x)); return t;
}
__device__ __forceinline__ unsigned smem_u32(const void* p)
{
    unsigned a;
    asm("{ .reg .u64 t; cvta.to.shared.u64 t, %1; cvt.u32.u64 %0, t; }"
        : "=r"(a) : "l"(p));
    return a;
}

// ---------------------------------------------------------------------------
// One scalar RNN step with HW tanh. Consume xq[J]; optionally refill xq[J]
// (float2 LDS.64 at compile-time offset ROFF); dual-accumulator matvec.
// ---------------------------------------------------------------------------
#define STEP(J, ROFF, DO_REFILL, DO_OUT, OI)                                   \
{                                                                              \
    float xv[HID];                                                             \
    _Pragma("unroll")                                                          \
    for (int jp = 0; jp < 5; jp++) {                                           \
        xv[2 * jp]     = xq[J][jp].x;                                          \
        xv[2 * jp + 1] = xq[J][jp].y;                                          \
    }                                                                          \
    float a0[HID], a1[HID];                                                    \
    _Pragma("unroll")                                                          \
    for (int j = 0; j < HID; j++) {                                            \
        a0[j] = fmaf(w[0][j], h[0], xv[j]);                                    \
        a1[j] = w[5][j] * h[5];                                                \
    }                                                                          \
    if (DO_REFILL) {                                                           \
        _Pragma("unroll")                                                      \
        for (int jp = 0; jp < 5; jp++)                                         \
            xq[J][jp] = *reinterpret_cast<const float2*>(                      \
                            pbase + (ROFF) + jp * JP_STR);                     \
    }                                                                          \
    _Pragma("unroll")                                                          \
    for (int k = 1; k < 5; k++) {                                              \
        _Pragma("unroll")                                                      \
        for (int j = 0; j < HID; j++) {                                        \
            a0[j] = fmaf(w[k][j],     h[k],     a0[j]);                        \
            a1[j] = fmaf(w[k + 5][j], h[k + 5], a1[j]);                        \
        }                                                                      \
    }                                                                          \
    _Pragma("unroll")                                                          \
    for (int j = 0; j < HID; j++)                                              \
        h[j] = tanhf_hw(a0[j] + a1[j]);                                        \
    if (DO_OUT) {                                                              \
        float o = bf;                                                          \
        _Pragma("unroll")                                                      \
        for (int j = 0; j < HID; j++) o = fmaf(wf[j], h[j], o);                \
        srow[OI] = o;                                                          \
    }                                                                          \
}

// ---------------------------------------------------------------------------
// Fused kernel: one warp = 32 chunks (one per lane). Bulk-DMA staging
// (cp.async.bulk, no L1tex wavefronts) overlapped with weight setup; xp
// compute in smem; 10 warmup + 16 output steps; coalesced flush.
// ---------------------------------------------------------------------------
__global__ void __launch_bounds__(32, 1) rnn_fused_kernel(
    const float* __restrict__ src,    // (SEQ, 1, IN_D)
    const float* __restrict__ W_ih,   // (HID, IN_D)
    const float* __restrict__ W_hh,   // (HID, HID)
    const float* __restrict__ b_ih,   // (HID,)
    const float* __restrict__ b_hh,   // (HID,)
    const float* __restrict__ W_fc,   // (1, HID)
    const float* __restrict__ b_fc,   // (1,)
    float* __restrict__ out)          // (SEQ,)
{
    __shared__ float2 sxp[16 * 5 * 33 + 4];            // 21152 B
    __shared__ alignas(16) float sraw[WIN_T * IN_D];   // 10560 B; reused for outputs
    __shared__ alignas(8) unsigned long long mbar;

    const int lane = threadIdx.x;
    const int c0   = blockIdx.x * 32;
    const long t0  = ((long)c0 - 1) * 16;              // window origin (−16 for block 0)

    // ---- issue the bulk DMA first (completion signaled on mbar) ----
    if (lane == 0) {
        asm volatile("mbarrier.init.shared.b64 [%0], %1;"
                     :: "r"(smem_u32(&mbar)), "r"(1) : "memory");
    }
    __syncwarp();
    if (lane == 0) {
        const bool  b0   = (blockIdx.x == 0);
        const int   skip = b0 ? 16 * IN_D * 4 : 0;     // 320 B
        const int   size = WIN_BYTES - skip;
        const char* gsrc = reinterpret_cast<const char*>(src) + t0 * IN_D * 4 + skip;
        const unsigned dst = smem_u32(sraw) + skip;
        asm volatile("mbarrier.arrive.expect_tx.shared.b64 _, [%0], %1;"
                     :: "r"(smem_u32(&mbar)), "r"(size) : "memory");
        asm volatile("cp.async.bulk.shared::cta.global.mbarrier::complete_tx::bytes"
                     " [%0], [%1], %2, [%3];"
                     :: "r"(dst), "l"(gsrc), "r"(size), "r"(smem_u32(&mbar))
                     : "memory");
    }

    // ---- overlap: load all weights into registers while the DMA flies ----
    float wih[HID][IN_D], bias[HID];
#pragma unroll
    for (int j = 0; j < HID; j++) {
        bias[j] = b_ih[j] + b_hh[j];
#pragma unroll
        for (int k = 0; k < IN_D; k++) wih[j][k] = W_ih[j * IN_D + k];
    }
    float w[HID][HID];                 // w[k][j] = W_hh[j][k]
#pragma unroll
    for (int k = 0; k < HID; k++)
#pragma unroll
        for (int j = 0; j < HID; j++)
            w[k][j] = W_hh[j * HID + k];
    float wf[HID];
#pragma unroll
    for (int j = 0; j < HID; j++) wf[j] = W_fc[j];
    const float bf = b_fc[0];

    // ---- wait for DMA ----
    {
        const unsigned mb = smem_u32(&mbar);
        unsigned done;
        asm volatile(
            "{\n\t"
            ".reg .pred p;\n\t"
            "WAIT_%=:\n\t"
            "mbarrier.try_wait.parity.acquire.cta.shared::cta.b64 p, [%1], 0;\n\t"
            "@p bra.uni DONE_%=;\n\t"
            "bra.uni WAIT_%=;\n\t"
            "DONE_%=:\n\t"
            "mov.u32 %0, 1;\n\t"
            "}"
            : "=r"(done) : "r"(mb) : "memory");
    }
    __syncwarp();

    // ---- compute xp into sxp (t < 0 -> exact zeros) ----
#pragma unroll 1
    for (int kk = 0; kk < 17; kk++) {
        const int u = lane + 32 * kk;
        if (u < WIN_T) {
            const float* sp = sraw + u * IN_D;
            const float s0 = sp[0], s1 = sp[1], s2 = sp[2], s3 = sp[3], s4 = sp[4];
            const bool neg = (t0 + u) < 0;
            float2* dst = &sxp[((u & 15) * 5) * 33 + (u >> 4)];
#pragma unroll
            for (int jp = 0; jp < 5; jp++) {
                float vl = bias[2 * jp], vh = bias[2 * jp + 1];
                vl = fmaf(s0, wih[2 * jp][0], vl);  vh = fmaf(s0, wih[2 * jp + 1][0], vh);
                vl = fmaf(s1, wih[2 * jp][1], vl);  vh = fmaf(s1, wih[2 * jp + 1][1], vh);
                vl = fmaf(s2, wih[2 * jp][2], vl);  vh = fmaf(s2, wih[2 * jp + 1][2], vh);
                vl = fmaf(s3, wih[2 * jp][3], vl);  vh = fmaf(s3, wih[2 * jp + 1][3], vh);
                vl = fmaf(s4, wih[2 * jp][4], vl);  vh = fmaf(s4, wih[2 * jp + 1][4], vh);
                if (neg) { vl = 0.0f; vh = 0.0f; }
                dst[jp * 33] = make_float2(vl, vh);
            }
        }
    }
    __syncwarp();

    // ---- scan state ----
    float h[HID];
#pragma unroll
    for (int j = 0; j < HID; j++) h[j] = 0.0f;

    const char* pbase = reinterpret_cast<const char*>(sxp) + lane * 8;
    float* srow = sraw + lane * 17;   // outputs: stride-17, conflict-free

    // preload warmup col slots 6,7
    float2 xq[2][5];
#pragma unroll
    for (int jp = 0; jp < 5; jp++) {
        xq[0][jp] = *reinterpret_cast<const float2*>(pbase + 6 * S_STR + jp * JP_STR);
        xq[1][jp] = *reinterpret_cast<const float2*>(pbase + 7 * S_STR + jp * JP_STR);
    }

    // ---- warmup: si = 0..9 (consume warmup col slots 6..15) ----
#pragma unroll 1
    for (int it = 0; it < 4; it++) {             // si = 0..7, refill slots 8..15
        const int off = (8 + 2 * it) * S_STR;
        STEP(0, off, true, false, 0)
        STEP(1, off + S_STR, true, false, 0)
    }
    STEP(0, 8 + 0 * S_STR, true, false, 0)       // si = 8, refill output slot 0
    STEP(1, 8 + 1 * S_STR, true, false, 0)       // si = 9, refill output slot 1

    // ---- output: si = 10..25 (consume output col slots 0..15) ----
#pragma unroll 1
    for (int it = 0; it < 7; it++) {             // si = 10..23, refill slots 2..15
        const int off = 8 + (2 + 2 * it) * S_STR;
        STEP(0, off, true, true, 0)
        STEP(1, off + S_STR, true, true, 1)
        srow += 2;
    }
    STEP(0, 8, false, true, 0)                   // si = 24 (no refill)
    STEP(1, 8, false, true, 1)                   // si = 25 (no refill)

    __syncwarp();

    // ---- coalesced flush: this block owns out[blockIdx*512 .. +512) ----
    float* ob = out + (size_t)blockIdx.x * 512;
#pragma unroll
    for (int i = 0; i < 16; i++) {
        const int idx = i * 32 + lane;
        ob[idx] = sraw[(idx >> 4) * 17 + (idx & 15)];
    }
}

// ---------------------------------------------------------------------------
extern "C" void kernel_launch(void* const* d_in, const int* in_sizes, int n_in,
                              void* d_out, int out_size)
{
    const float* src  = (const float*)d_in[0];
    const float* W_ih = (const float*)d_in[1];
    const float* W_hh = (const float*)d_in[2];
    const float* b_ih = (const float*)d_in[3];
    const float* b_hh = (const float*)d_in[4];
    const float* W_fc = (const float*)d_in[5];
    const float* b_fc = (const float*)d_in[6];
    float* out = (float*)d_out;

    rnn_fused_kernel<<<NBLK, 32>>>(src, W_ih, W_hh, b_ih, b_hh, W_fc, b_fc, out);
}